// round 14
// baseline (speedup 1.0000x reference)
#include <cuda_runtime.h>
#include <cuda_fp16.h>
#include <cstdint>

#define BB 2
#define CC 64
#define HWD 64
#define NVOX (HWD*HWD*HWD)   /* 262144 */
#define TILE_V 128
#define NBLK_L 512           /* k_logits blocks per batch (512 vox each) */

// ---------------- device scratch (static, no allocation) ----------------
__device__ float    g_s[BB][CC];
__device__ float    g_mh[BB][HWD];
__device__ float    g_mw[BB][HWD];
__device__ float    g_md[BB][HWD];
__device__ float    g_M[BB];
__device__ float    g_u[BB][CC];
__device__ float    g_c0[BB];
__device__ float    g_qh[BB][HWD];
__device__ float    g_qw[BB][HWD];
__device__ float    g_qd[BB][HWD];
__device__ float    g_bmax[BB][NBLK_L];
__device__ float    g_bsum[BB][NBLK_L];
__device__ float    g_gmax[BB];
__device__ float    g_scale[BB];          // M / sumexp
__device__ float    g_logits[BB][NVOX];   // raw logits
__device__ unsigned short g_Wh[CC * CC];  // Wv fp16, swizzled [n][k^8(n&7)]
__device__ unsigned short g_xh[(size_t)BB * CC * NVOX];  // x in fp16 (67MB)

// ---------------- helpers ----------------
__device__ __forceinline__ uint32_t smem_u32(const void* p) {
    uint32_t a;
    asm("{ .reg .u64 t; cvta.to.shared.u64 t, %1; cvt.u32.u64 %0, t; }"
        : "=r"(a) : "l"(p));
    return a;
}
__device__ __forceinline__ uint32_t f16x2_pack(float v0, float v1) {
    uint32_t h;
    asm("cvt.rn.f16x2.f32 %0, %1, %2;" : "=r"(h) : "f"(v1), "f"(v0));
    return h;
}
__device__ __forceinline__ void ldmA(uint32_t* a, uint32_t addr) {
    asm volatile("ldmatrix.sync.aligned.m8n8.x4.trans.shared.b16 "
                 "{%0,%1,%2,%3}, [%4];"
                 : "=r"(a[0]), "=r"(a[1]), "=r"(a[2]), "=r"(a[3]) : "r"(addr));
}
__device__ __forceinline__ void ldmB4(uint32_t* b, uint32_t addr) {
    asm volatile("ldmatrix.sync.aligned.m8n8.x4.shared.b16 {%0,%1,%2,%3}, [%4];"
                 : "=r"(b[0]), "=r"(b[1]), "=r"(b[2]), "=r"(b[3]) : "r"(addr));
}
__device__ __forceinline__ void mma_f16(float* c, const uint32_t* a,
                                        const uint32_t* b) {
    asm volatile("mma.sync.aligned.m16n8k16.row.col.f32.f16.f16.f32 "
                 "{%0,%1,%2,%3}, {%4,%5,%6,%7}, {%8,%9}, {%0,%1,%2,%3};"
                 : "+f"(c[0]), "+f"(c[1]), "+f"(c[2]), "+f"(c[3])
                 : "r"(a[0]), "r"(a[1]), "r"(a[2]), "r"(a[3]),
                   "r"(b[0]), "r"(b[1]));
}

// ---------------- kernel W: zero scratch + convert Wv to fp16 (merged) ------
__global__ void k_wsplit(const float* __restrict__ Wv) {
    const int tid = threadIdx.x;
    if (blockIdx.x == 16) {       // zeroing block
        if (tid < CC)  { g_s[0][tid] = 0.f; g_s[1][tid] = 0.f; }
        if (tid < HWD) {
            g_mh[0][tid] = 0.f; g_mh[1][tid] = 0.f;
            g_mw[0][tid] = 0.f; g_mw[1][tid] = 0.f;
            g_md[0][tid] = 0.f; g_md[1][tid] = 0.f;
        }
        return;
    }
    int i = blockIdx.x * 256 + tid;
    int n = i >> 6, k = i & 63;
    const __half h = __float2half_rn(Wv[i]);
    int ks = k ^ (8 * (n & 7));
    g_Wh[n * 64 + ks] = __half_as_ushort(h);
}

// ---------------- kernel 1: masked reductions ----------------
__global__ void __launch_bounds__(256) k_reduce(const float* __restrict__ x,
                                                const float* __restrict__ mask) {
    const int b   = blockIdx.y;
    const float* xb = x    + (size_t)b * CC * NVOX;
    const float* mb = mask + (size_t)b * NVOX;
    __shared__ float ss[CC];
    __shared__ float sh[HWD], sw[HWD], sd[HWD];
    const int tid = threadIdx.x;
    for (int i = tid; i < CC;  i += 256) ss[i] = 0.f;
    for (int i = tid; i < HWD; i += 256) { sh[i] = 0.f; sw[i] = 0.f; sd[i] = 0.f; }
    __syncthreads();

    float acc[CC];
    #pragma unroll
    for (int c = 0; c < CC; c++) acc[c] = 0.f;

    const int nPairs = NVOX / 2;
    for (int p = blockIdx.x * 256 + tid; p < nPairs; p += gridDim.x * 256) {
        const int n = 2 * p;
        const float2 m2 = ((const float2*)mb)[p];
        const int d = n & 63, w = (n >> 6) & 63, h = n >> 12;
        float wsum = m2.x + m2.y;
        #pragma unroll
        for (int o = 16; o; o >>= 1) wsum += __shfl_xor_sync(0xffffffffu, wsum, o);
        if ((tid & 31) == 0) { atomicAdd(&sh[h], wsum); atomicAdd(&sw[w], wsum); }
        atomicAdd(&sd[d],     m2.x);
        atomicAdd(&sd[d + 1], m2.y);
        #pragma unroll
        for (int c = 0; c < CC; c++) {
            const float2 v = ((const float2*)(xb + (size_t)c * NVOX))[p];
            acc[c] += m2.x * v.x + m2.y * v.y;
        }
    }
    #pragma unroll
    for (int c = 0; c < CC; c++) {
        float v = acc[c];
        #pragma unroll
        for (int o = 16; o; o >>= 1) v += __shfl_xor_sync(0xffffffffu, v, o);
        if ((tid & 31) == 0) atomicAdd(&ss[c], v);
    }
    __syncthreads();
    for (int i = tid; i < CC;  i += 256) atomicAdd(&g_s[b][i], ss[i]);
    for (int i = tid; i < HWD; i += 256) {
        atomicAdd(&g_mh[b][i], sh[i]);
        atomicAdd(&g_mw[b][i], sw[i]);
        atomicAdd(&g_md[b][i], sd[i]);
    }
}

// ---------------- kernel 2: prep (256 thr = 64 outputs x 4 slices) ----------
__global__ void __launch_bounds__(256) k_prep(const float* __restrict__ Wk,
                                              const float* __restrict__ bk,
                                              const float* __restrict__ Wq,
                                              const float* __restrict__ bq,
                                              const float* __restrict__ h_tab,
                                              const float* __restrict__ w_tab,
                                              const float* __restrict__ d_tab) {
    const int b   = blockIdx.x;
    const int tid = threadIdx.x;
    const int t   = tid >> 2;
    const int sl  = tid & 3;
    __shared__ float qs[CC];
    __shared__ float red[CC];
    __shared__ float Msh;

    if (tid < HWD) red[tid] = g_mh[b][tid];
    __syncthreads();
    if (tid == 0) {
        float M = 0.f;
        #pragma unroll
        for (int i = 0; i < HWD; i++) M += red[i];
        Msh = M; g_M[b] = M;
    }
    __syncthreads();

    {
        float a = 0.f;
        #pragma unroll
        for (int i = 0; i < 16; i++) {
            const int c = sl * 16 + i;
            a += Wq[t * CC + c] * g_s[b][c];
            a += g_mh[b][c] * h_tab[c * CC + t];
            a += g_mw[b][c] * w_tab[c * CC + t];
            a += g_md[b][c] * d_tab[c * CC + t];
        }
        a += __shfl_xor_sync(0xffffffffu, a, 1);
        a += __shfl_xor_sync(0xffffffffu, a, 2);
        if (sl == 0) qs[t] = a / Msh + bq[t];
    }
    __syncthreads();

    {
        float u = 0.f, a1 = 0.f, a2 = 0.f, a3 = 0.f;
        #pragma unroll
        for (int i = 0; i < 16; i++) {
            const int ck = sl * 16 + i;
            const float q = qs[ck];
            u  += q * Wk[ck * CC + t];
            a1 += q * h_tab[t * CC + ck];
            a2 += q * w_tab[t * CC + ck];
            a3 += q * d_tab[t * CC + ck];
        }
        u  += __shfl_xor_sync(0xffffffffu, u, 1);
        u  += __shfl_xor_sync(0xffffffffu, u, 2);
        a1 += __shfl_xor_sync(0xffffffffu, a1, 1);
        a1 += __shfl_xor_sync(0xffffffffu, a1, 2);
        a2 += __shfl_xor_sync(0xffffffffu, a2, 1);
        a2 += __shfl_xor_sync(0xffffffffu, a2, 2);
        a3 += __shfl_xor_sync(0xffffffffu, a3, 1);
        a3 += __shfl_xor_sync(0xffffffffu, a3, 2);
        if (sl == 0) {
            g_u[b][t]  = u;
            g_qh[b][t] = a1; g_qw[b][t] = a2; g_qd[b][t] = a3;
        }
    }
    if (tid < CC) red[tid] = qs[tid] * bk[tid];
    __syncthreads();
    if (tid == 0) {
        float a = 0.f;
        #pragma unroll
        for (int i = 0; i < CC; i++) a += red[i];
        g_c0[b] = a;
    }
}

// ---------------- kernel 3: logits + block stats + fp16 x staging ------------
__global__ void __launch_bounds__(256) k_logits(const float* __restrict__ x) {
    const int b = blockIdx.y;
    __shared__ float us[CC];
    __shared__ float wred[8];
    __shared__ float bmax_s;
    const int tid = threadIdx.x;
    if (tid < CC) us[tid] = g_u[b][tid];
    __syncthreads();
    const float* xb = x + (size_t)b * CC * NVOX;
    unsigned short* xhb = g_xh + (size_t)b * CC * NVOX;
    const float  c0 = g_c0[b];
    const int p = blockIdx.x * 256 + tid;
    const int n = 2 * p;
    float l0 = c0, l1 = c0;
    #pragma unroll
    for (int c = 0; c < CC; c++) {
        const float2 v = ((const float2*)(xb + (size_t)c * NVOX))[p];
        const float u = us[c];
        l0 += u * v.x;
        l1 += u * v.y;
        // stage fp16 copy for k_out (same cvt.rn rounding as before)
        *(uint32_t*)&xhb[(size_t)c * NVOX + n] = f16x2_pack(v.x, v.y);
    }
    const int d = n & 63, w = (n >> 6) & 63, h = n >> 12;
    const float pw = g_qh[b][h] + g_qw[b][w];
    l0 = (l0 + pw + g_qd[b][d])     * 0.125f;
    l1 = (l1 + pw + g_qd[b][d + 1]) * 0.125f;
    ((float2*)&g_logits[b][0])[p] = make_float2(l0, l1);

    // block max
    float mx = fmaxf(l0, l1);
    #pragma unroll
    for (int o = 16; o; o >>= 1) mx = fmaxf(mx, __shfl_xor_sync(0xffffffffu, mx, o));
    const int wid = tid >> 5;
    if ((tid & 31) == 0) wred[wid] = mx;
    __syncthreads();
    if (tid == 0) {
        float m = wred[0];
        #pragma unroll
        for (int j = 1; j < 8; j++) m = fmaxf(m, wred[j]);
        bmax_s = m;
    }
    __syncthreads();
    const float bm = bmax_s;

    // block sum of exp(l - bm)
    float s = expf(l0 - bm) + expf(l1 - bm);
    #pragma unroll
    for (int o = 16; o; o >>= 1) s += __shfl_xor_sync(0xffffffffu, s, o);
    if ((tid & 31) == 0) wred[wid] = s;
    __syncthreads();
    if (tid == 0) {
        float t = 0.f;
        #pragma unroll
        for (int j = 0; j < 8; j++) t += wred[j];
        g_bmax[b][blockIdx.x] = bm;
        g_bsum[b][blockIdx.x] = t;
    }
}

// ---------------- kernel 4: finish softmax stats (tiny) ----------------
__global__ void __launch_bounds__(NBLK_L) k_finish() {
    const int b = blockIdx.x;
    const int t = threadIdx.x;        // 512
    __shared__ float wred[16];
    __shared__ float gmax_s;
    const float bm = g_bmax[b][t];
    float m = bm;
    #pragma unroll
    for (int o = 16; o; o >>= 1) m = fmaxf(m, __shfl_xor_sync(0xffffffffu, m, o));
    if ((t & 31) == 0) wred[t >> 5] = m;
    __syncthreads();
    if (t == 0) {
        float g = wred[0];
        #pragma unroll
        for (int j = 1; j < 16; j++) g = fmaxf(g, wred[j]);
        gmax_s = g;
    }
    __syncthreads();
    const float gm = gmax_s;
    float s = g_bsum[b][t] * expf(bm - gm);
    #pragma unroll
    for (int o = 16; o; o >>= 1) s += __shfl_xor_sync(0xffffffffu, s, o);
    if ((t & 31) == 0) wred[t >> 5] = s;
    __syncthreads();
    if (t == 0) {
        float tot = 0.f;
        #pragma unroll
        for (int j = 0; j < 16; j++) tot += wred[j];
        g_gmax[b]  = gm;
        g_scale[b] = g_M[b] / tot;
    }
}

// ---------------- kernel 5: vals GEMM on mma.sync pure fp16 -----------------
// x already fp16 in g_xh (staged by k_logits): no fp32 read, no convert phase.
// Block tile: 128 vox (M) x 64 co (N), K=64.  8 warps, each 16 vox rows.
// smem: Xh 16K | Wh 8K; Ds overlay 33,792B -> 34,048B dyn. Occupancy 4.
#define SM_XH 0
#define SM_WH 16384
#define OUT_SMEM_DYN 34048

__global__ void __launch_bounds__(256, 4) k_out_mma(const float* __restrict__ bv,
                                                    float* __restrict__ out) {
    extern __shared__ char dsm[];
    __shared__ float sc_s[TILE_V];
    __shared__ float s_bv[CC];

    const int tid = threadIdx.x;
    const int b   = blockIdx.y;
    const int n0  = blockIdx.x * TILE_V;
    const uint32_t sbase = smem_u32(dsm);

    unsigned short* Xh = (unsigned short*)(dsm + SM_XH);

    // ---- front-load fp16 x tile: 4 uint4 per thread (16KB total) ----
    const unsigned short* xhb = g_xh + (size_t)b * CC * NVOX + n0;
    const int vld = (tid & 15) * 8;        // vox (halves), 16 thr cover 128
    const int cld = tid >> 4;              // c base, 4 phases stride 16
    uint4 xq[4];
    #pragma unroll
    for (int ph = 0; ph < 4; ph++)
        xq[ph] = *(const uint4*)(xhb + (size_t)(cld + ph * 16) * NVOX + vld);

    // ---- weights + bias + per-vox softmax scale (overlaps x-load latency) ----
    {
        const uint4* wh = (const uint4*)g_Wh;
        uint4* dh = (uint4*)(dsm + SM_WH);
        for (int i = tid; i < 512; i += 256) dh[i] = wh[i];
        if (tid < CC) s_bv[tid] = bv[tid];
        if (tid < 32) {
            const float scl = g_scale[b];
            const float gm  = g_gmax[b];
            float4 pv = *(const float4*)&g_logits[b][n0 + tid * 4];
            sc_s[tid * 4 + 0] = scl * expf(pv.x - gm);
            sc_s[tid * 4 + 1] = scl * expf(pv.y - gm);
            sc_s[tid * 4 + 2] = scl * expf(pv.z - gm);
            sc_s[tid * 4 + 3] = scl * expf(pv.w - gm);
        }
    }
    // ---- swizzled store (no convert): elem (c, v) at [c*128 + (v ^ 8*(c&7))] --
    #pragma unroll
    for (int ph = 0; ph < 4; ph++) {
        const int c = cld + ph * 16;
        const int off = c * 128 + (vld ^ (8 * (c & 7)));
        *(uint4*)&Xh[off] = xq[ph];
    }
    __syncthreads();

    // ---- mma mainloop: warp = 16 vox rows x 64 co ----
    const int wrp  = tid >> 5;
    const int lane = tid & 31;
    const int v0   = wrp * 16;

    float acc[8][4];
    #pragma unroll
    for (int ni = 0; ni < 8; ni++)
        #pragma unroll
        for (int r = 0; r < 4; r++) acc[ni][r] = 0.f;

    const int jA   = lane & 7;
    const int sub  = lane >> 3;                // 0..3
    const int cOfA = (sub >> 1) * 8 + jA;
    const int vOfA = (sub & 1) * 8;
    const int niOfB = sub >> 1;
    const int kSelB = sub & 1;

    #pragma unroll
    for (int ki = 0; ki < 4; ki++) {
        const int k0 = ki * 16;
        uint32_t Ah[4];
        {
            const int c = k0 + cOfA;
            const int v = v0 + vOfA;
            const uint32_t off = (uint32_t)(c * 128 + (v ^ (8 * (c & 7)))) * 2u;
            ldmA(Ah, sbase + SM_XH + off);
        }
        #pragma unroll
        for (int np = 0; np < 4; np++) {       // ni pair {2np, 2np+1}
            const int n = (np * 2 + niOfB) * 8 + jA;
            const int k = k0 + 8 * kSelB;
            const uint32_t off = (uint32_t)(n * 64 + (k ^ (8 * (n & 7)))) * 2u;
            uint32_t Bh[4];
            ldmB4(Bh, sbase + SM_WH + off);
            mma_f16(acc[np * 2],     Ah, Bh);
            mma_f16(acc[np * 2 + 1], Ah, Bh + 2);
        }
    }
    __syncthreads();           // done with Xh/Wh smem; overlay Ds

    // ---- stage D to smem: Ds[co][vox], row stride 132 floats ----
    float* Ds = (float*)dsm;
    {
        const int g = lane >> 2, t4 = lane & 3;
        const int m = v0 + g;
        #pragma unroll
        for (int ni = 0; ni < 8; ni++) {
            const int n = ni * 8 + t4 * 2;
            Ds[n * 132 + m]           = acc[ni][0];
            Ds[(n + 1) * 132 + m]     = acc[ni][1];
            Ds[n * 132 + m + 8]       = acc[ni][2];
            Ds[(n + 1) * 132 + m + 8] = acc[ni][3];
        }
    }
    __syncthreads();

    // ---- epilogue: warp = 8 co rows, lane covers full 128-vox row (512B stores)
    {
        const int v = lane * 4;
        const float4 sv = *(const float4*)&sc_s[v];
        #pragma unroll
        for (int r = 0; r < 8; r++) {
            const int co = wrp * 8 + r;
            const float bvv = s_bv[co];
            float4 dv = *(const float4*)&Ds[co * 132 + v];
            dv.x = (dv.x + bvv) * sv.x;
            dv.y = (dv.y + bvv) * sv.y;
            dv.z = (dv.z + bvv) * sv.z;
            dv.w = (dv.w + bvv) * sv.w;
            *(float4*)&out[((size_t)(b * CC + co)) * NVOX + n0 + v] = dv;
        }
    }
}

// ---------------- host launcher ----------------
extern "C" void kernel_launch(void* const* d_in, const int* in_sizes, int n_in,
                              void* d_out, int out_size) {
    const float* x     = (const float*)d_in[0];
    const float* mask  = (const float*)d_in[1];
    const float* Wk    = (const float*)d_in[2];
    const float* bk    = (const float*)d_in[3];
    const float* Wv    = (const float*)d_in[4];
    const float* bv    = (const float*)d_in[5];
    const float* Wq    = (const float*)d_in[6];
    const float* bq    = (const float*)d_in[7];
    const float* h_tab = (const float*)d_in[8];
    const float* w_tab = (const float*)d_in[9];
    const float* d_tab = (const float*)d_in[10];
    float* out = (float*)d_out;

    cudaFuncSetAttribute(k_out_mma, cudaFuncAttributeMaxDynamicSharedMemorySize,
                         OUT_SMEM_DYN);

    k_wsplit <<<17, 256>>>(Wv);                     // includes scratch zeroing
    k_reduce <<<dim3(256, BB), 256>>>(x, mask);
    k_prep   <<<BB, 256>>>(Wk, bk, Wq, bq, h_tab, w_tab, d_tab);
    k_logits <<<dim3(NBLK_L, BB), 256>>>(x);
    k_finish <<<BB, NBLK_L>>>();
    k_out_mma<<<dim3(NVOX / TILE_V, BB), 256, OUT_SMEM_DYN>>>(bv, out);

    // output tuple tail: mask passthrough
    cudaMemcpyAsync(out + (size_t)BB * CC * NVOX, mask,
                    (size_t)BB * NVOX * sizeof(float),
                    cudaMemcpyDeviceToDevice, 0);
}

// round 15
// speedup vs baseline: 1.1397x; 1.1397x over previous
#include <cuda_runtime.h>
#include <cuda_fp16.h>
#include <cstdint>

#define BB 2
#define CC 64
#define HWD 64
#define NVOX (HWD*HWD*HWD)   /* 262144 */
#define TILE_V 128
#define NBLK_L 256           /* k_logits blocks per batch (1024 vox each) */

// ---------------- device scratch (static, no allocation) ----------------
__device__ float    g_s[BB][CC];
__device__ float    g_mh[BB][HWD];
__device__ float    g_mw[BB][HWD];
__device__ float    g_md[BB][HWD];
__device__ float    g_M[BB];
__device__ float    g_u[BB][CC];
__device__ float    g_c0[BB];
__device__ float    g_qh[BB][HWD];
__device__ float    g_qw[BB][HWD];
__device__ float    g_qd[BB][HWD];
__device__ float    g_bmax[BB][NBLK_L];
__device__ float    g_bsum[BB][NBLK_L];
__device__ float    g_gmax[BB];
__device__ float    g_scale[BB];          // M / sumexp
__device__ float    g_logits[BB][NVOX];   // raw logits
__device__ unsigned short g_Wh[CC * CC];  // Wv fp16, swizzled [n][k^8(n&7)]

// ---------------- helpers ----------------
__device__ __forceinline__ uint32_t smem_u32(const void* p) {
    uint32_t a;
    asm("{ .reg .u64 t; cvta.to.shared.u64 t, %1; cvt.u32.u64 %0, t; }"
        : "=r"(a) : "l"(p));
    return a;
}
__device__ __forceinline__ uint32_t f16x2_pack(float v0, float v1) {
    uint32_t h;
    asm("cvt.rn.f16x2.f32 %0, %1, %2;" : "=r"(h) : "f"(v1), "f"(v0));
    return h;
}
__device__ __forceinline__ void ldmA(uint32_t* a, uint32_t addr) {
    asm volatile("ldmatrix.sync.aligned.m8n8.x4.trans.shared.b16 "
                 "{%0,%1,%2,%3}, [%4];"
                 : "=r"(a[0]), "=r"(a[1]), "=r"(a[2]), "=r"(a[3]) : "r"(addr));
}
__device__ __forceinline__ void ldmB4(uint32_t* b, uint32_t addr) {
    asm volatile("ldmatrix.sync.aligned.m8n8.x4.shared.b16 {%0,%1,%2,%3}, [%4];"
                 : "=r"(b[0]), "=r"(b[1]), "=r"(b[2]), "=r"(b[3]) : "r"(addr));
}
__device__ __forceinline__ void mma_f16(float* c, const uint32_t* a,
                                        const uint32_t* b) {
    asm volatile("mma.sync.aligned.m16n8k16.row.col.f32.f16.f16.f32 "
                 "{%0,%1,%2,%3}, {%4,%5,%6,%7}, {%8,%9}, {%0,%1,%2,%3};"
                 : "+f"(c[0]), "+f"(c[1]), "+f"(c[2]), "+f"(c[3])
                 : "r"(a[0]), "r"(a[1]), "r"(a[2]), "r"(a[3]),
                   "r"(b[0]), "r"(b[1]));
}

// ---------------- kernel W: zero scratch + convert Wv to fp16 (merged) ------
__global__ void k_wsplit(const float* __restrict__ Wv) {
    const int tid = threadIdx.x;
    if (blockIdx.x == 16) {       // zeroing block
        if (tid < CC)  { g_s[0][tid] = 0.f; g_s[1][tid] = 0.f; }
        if (tid < HWD) {
            g_mh[0][tid] = 0.f; g_mh[1][tid] = 0.f;
            g_mw[0][tid] = 0.f; g_mw[1][tid] = 0.f;
            g_md[0][tid] = 0.f; g_md[1][tid] = 0.f;
        }
        return;
    }
    int i = blockIdx.x * 256 + tid;
    int n = i >> 6, k = i & 63;
    const __half h = __float2half_rn(Wv[i]);
    int ks = k ^ (8 * (n & 7));
    g_Wh[n * 64 + ks] = __half_as_ushort(h);
}

// ---------------- kernel 1: masked reductions (float4, exact cover) ---------
__global__ void __launch_bounds__(256) k_reduce(const float* __restrict__ x,
                                                const float* __restrict__ mask) {
    const int b   = blockIdx.y;
    const float* xb = x    + (size_t)b * CC * NVOX;
    const float* mb = mask + (size_t)b * NVOX;
    __shared__ float ss[CC];
    __shared__ float sh[HWD], sw[HWD], sd[HWD];
    const int tid = threadIdx.x;
    if (tid < CC)  ss[tid] = 0.f;
    if (tid < HWD) { sh[tid] = 0.f; sw[tid] = 0.f; sd[tid] = 0.f; }
    __syncthreads();

    const int p = blockIdx.x * 256 + tid;      // quad index (exact cover)
    const int n = 4 * p;
    const float4 m = ((const float4*)mb)[p];
    const int d = n & 63, w = (n >> 6) & 63, h = n >> 12;
    const int lane = tid & 31;
    const float msum = m.x + m.y + m.z + m.w;

    // h marginal: warp-uniform (n spans 128 per warp, h = n>>12)
    {
        float s = msum;
        #pragma unroll
        for (int o = 16; o; o >>= 1) s += __shfl_xor_sync(0xffffffffu, s, o);
        if (lane == 0) atomicAdd(&sh[h], s);
    }
    // w marginal: uniform per 16-lane half (n spans 64 per half-warp)
    {
        float s = msum;
        #pragma unroll
        for (int o = 8; o; o >>= 1) s += __shfl_xor_sync(0xffffffffu, s, o);
        if ((lane & 15) == 0) atomicAdd(&sw[w], s);
    }
    // d marginal
    atomicAdd(&sd[d],     m.x);
    atomicAdd(&sd[d + 1], m.y);
    atomicAdd(&sd[d + 2], m.z);
    atomicAdd(&sd[d + 3], m.w);

    // channel-wise masked sums
    float acc[CC];
    #pragma unroll
    for (int c = 0; c < CC; c++) {
        const float4 v = ((const float4*)(xb + (size_t)c * NVOX))[p];
        acc[c] = m.x * v.x + m.y * v.y + m.z * v.z + m.w * v.w;
    }
    #pragma unroll
    for (int c = 0; c < CC; c++) {
        float v = acc[c];
        #pragma unroll
        for (int o = 16; o; o >>= 1) v += __shfl_xor_sync(0xffffffffu, v, o);
        if (lane == 0) atomicAdd(&ss[c], v);
    }
    __syncthreads();
    if (tid < CC)  atomicAdd(&g_s[b][tid],  ss[tid]);
    if (tid < HWD) {
        atomicAdd(&g_mh[b][tid], sh[tid]);
        atomicAdd(&g_mw[b][tid], sw[tid]);
        atomicAdd(&g_md[b][tid], sd[tid]);
    }
}

// ---------------- kernel 2: prep (256 thr = 64 outputs x 4 slices) ----------
__global__ void __launch_bounds__(256) k_prep(const float* __restrict__ Wk,
                                              const float* __restrict__ bk,
                                              const float* __restrict__ Wq,
                                              const float* __restrict__ bq,
                                              const float* __restrict__ h_tab,
                                              const float* __restrict__ w_tab,
                                              const float* __restrict__ d_tab) {
    const int b   = blockIdx.x;
    const int tid = threadIdx.x;
    const int t   = tid >> 2;
    const int sl  = tid & 3;
    __shared__ float qs[CC];
    __shared__ float red[CC];
    __shared__ float Msh;

    if (tid < HWD) red[tid] = g_mh[b][tid];
    __syncthreads();
    if (tid == 0) {
        float M = 0.f;
        #pragma unroll
        for (int i = 0; i < HWD; i++) M += red[i];
        Msh = M; g_M[b] = M;
    }
    __syncthreads();

    {
        float a = 0.f;
        #pragma unroll
        for (int i = 0; i < 16; i++) {
            const int c = sl * 16 + i;
            a += Wq[t * CC + c] * g_s[b][c];
            a += g_mh[b][c] * h_tab[c * CC + t];
            a += g_mw[b][c] * w_tab[c * CC + t];
            a += g_md[b][c] * d_tab[c * CC + t];
        }
        a += __shfl_xor_sync(0xffffffffu, a, 1);
        a += __shfl_xor_sync(0xffffffffu, a, 2);
        if (sl == 0) qs[t] = a / Msh + bq[t];
    }
    __syncthreads();

    {
        float u = 0.f, a1 = 0.f, a2 = 0.f, a3 = 0.f;
        #pragma unroll
        for (int i = 0; i < 16; i++) {
            const int ck = sl * 16 + i;
            const float q = qs[ck];
            u  += q * Wk[ck * CC + t];
            a1 += q * h_tab[t * CC + ck];
            a2 += q * w_tab[t * CC + ck];
            a3 += q * d_tab[t * CC + ck];
        }
        u  += __shfl_xor_sync(0xffffffffu, u, 1);
        u  += __shfl_xor_sync(0xffffffffu, u, 2);
        a1 += __shfl_xor_sync(0xffffffffu, a1, 1);
        a1 += __shfl_xor_sync(0xffffffffu, a1, 2);
        a2 += __shfl_xor_sync(0xffffffffu, a2, 1);
        a2 += __shfl_xor_sync(0xffffffffu, a2, 2);
        a3 += __shfl_xor_sync(0xffffffffu, a3, 1);
        a3 += __shfl_xor_sync(0xffffffffu, a3, 2);
        if (sl == 0) {
            g_u[b][t]  = u;
            g_qh[b][t] = a1; g_qw[b][t] = a2; g_qd[b][t] = a3;
        }
    }
    if (tid < CC) red[tid] = qs[tid] * bk[tid];
    __syncthreads();
    if (tid == 0) {
        float a = 0.f;
        #pragma unroll
        for (int i = 0; i < CC; i++) a += red[i];
        g_c0[b] = a;
    }
}

// ---------------- kernel 3: logits (float4) + block max + block expsum ------
__global__ void __launch_bounds__(256) k_logits(const float* __restrict__ x) {
    const int b = blockIdx.y;
    __shared__ float us[CC];
    __shared__ float wred[8];
    __shared__ float bmax_s;
    const int tid = threadIdx.x;
    if (tid < CC) us[tid] = g_u[b][tid];
    __syncthreads();
    const float* xb = x + (size_t)b * CC * NVOX;
    const float  c0 = g_c0[b];
    const int p = blockIdx.x * 256 + tid;      // quad index
    const int n = 4 * p;
    float l0 = c0, l1 = c0, l2 = c0, l3 = c0;
    #pragma unroll
    for (int c = 0; c < CC; c++) {
        const float4 v = ((const float4*)(xb + (size_t)c * NVOX))[p];
        const float u = us[c];
        l0 += u * v.x;
        l1 += u * v.y;
        l2 += u * v.z;
        l3 += u * v.w;
    }
    const int d = n & 63, w = (n >> 6) & 63, h = n >> 12;
    const float pw = g_qh[b][h] + g_qw[b][w];
    l0 = (l0 + pw + g_qd[b][d])     * 0.125f;
    l1 = (l1 + pw + g_qd[b][d + 1]) * 0.125f;
    l2 = (l2 + pw + g_qd[b][d + 2]) * 0.125f;
    l3 = (l3 + pw + g_qd[b][d + 3]) * 0.125f;
    ((float4*)&g_logits[b][0])[p] = make_float4(l0, l1, l2, l3);

    // block max
    float mx = fmaxf(fmaxf(l0, l1), fmaxf(l2, l3));
    #pragma unroll
    for (int o = 16; o; o >>= 1) mx = fmaxf(mx, __shfl_xor_sync(0xffffffffu, mx, o));
    const int wid = tid >> 5;
    if ((tid & 31) == 0) wred[wid] = mx;
    __syncthreads();
    if (tid == 0) {
        float m = wred[0];
        #pragma unroll
        for (int j = 1; j < 8; j++) m = fmaxf(m, wred[j]);
        bmax_s = m;
    }
    __syncthreads();
    const float bm = bmax_s;

    // block sum of exp(l - bm)
    float s = expf(l0 - bm) + expf(l1 - bm) + expf(l2 - bm) + expf(l3 - bm);
    #pragma unroll
    for (int o = 16; o; o >>= 1) s += __shfl_xor_sync(0xffffffffu, s, o);
    if ((tid & 31) == 0) wred[wid] = s;
    __syncthreads();
    if (tid == 0) {
        float t = 0.f;
        #pragma unroll
        for (int j = 0; j < 8; j++) t += wred[j];
        g_bmax[b][blockIdx.x] = bm;
        g_bsum[b][blockIdx.x] = t;
    }
}

// ---------------- kernel 4: finish softmax stats (tiny) ----------------
__global__ void __launch_bounds__(NBLK_L) k_finish() {
    const int b = blockIdx.x;
    const int t = threadIdx.x;        // 256
    __shared__ float wred[8];
    __shared__ float gmax_s;
    const float bm = g_bmax[b][t];
    float m = bm;
    #pragma unroll
    for (int o = 16; o; o >>= 1) m = fmaxf(m, __shfl_xor_sync(0xffffffffu, m, o));
    if ((t & 31) == 0) wred[t >> 5] = m;
    __syncthreads();
    if (t == 0) {
        float g = wred[0];
        #pragma unroll
        for (int j = 1; j < 8; j++) g = fmaxf(g, wred[j]);
        gmax_s = g;
    }
    __syncthreads();
    const float gm = gmax_s;
    float s = g_bsum[b][t] * expf(bm - gm);
    #pragma unroll
    for (int o = 16; o; o >>= 1) s += __shfl_xor_sync(0xffffffffu, s, o);
    if ((t & 31) == 0) wred[t >> 5] = s;
    __syncthreads();
    if (t == 0) {
        float tot = 0.f;
        #pragma unroll
        for (int j = 0; j < 8; j++) tot += wred[j];
        g_gmax[b]  = gm;
        g_scale[b] = g_M[b] / tot;
    }
}

// ---------------- kernel 5: vals GEMM on mma.sync pure fp16 (R13 shape) -----
#define SM_XH 0
#define SM_WH 16384
#define OUT_SMEM_DYN 34048

__global__ void __launch_bounds__(256, 4) k_out_mma(const float* __restrict__ x,
                                                    const float* __restrict__ bv,
                                                    float* __restrict__ out) {
    extern __shared__ char dsm[];
    __shared__ float sc_s[TILE_V];
    __shared__ float s_bv[CC];

    const int tid = threadIdx.x;
    const int b   = blockIdx.y;
    const int n0  = blockIdx.x * TILE_V;
    const uint32_t sbase = smem_u32(dsm);

    unsigned short* Xh = (unsigned short*)(dsm + SM_XH);

    // ---- front-load x tile: 8 float4 per thread ----
    const float* xb = x + (size_t)b * CC * NVOX + n0;
    const int vld = (tid & 31) * 4;
    const int cld = tid >> 5;
    float4 xv[8];
    #pragma unroll
    for (int ph = 0; ph < 8; ph++)
        xv[ph] = *(const float4*)&xb[(size_t)(cld + ph * 8) * NVOX + vld];

    // ---- weights + bias + per-vox softmax scale (overlaps x-load latency) ----
    {
        const uint4* wh = (const uint4*)g_Wh;
        uint4* dh = (uint4*)(dsm + SM_WH);
        for (int i = tid; i < 512; i += 256) dh[i] = wh[i];
        if (tid < CC) s_bv[tid] = bv[tid];
        if (tid < 32) {
            const float scl = g_scale[b];
            const float gm  = g_gmax[b];
            float4 pv = *(const float4*)&g_logits[b][n0 + tid * 4];
            sc_s[tid * 4 + 0] = scl * expf(pv.x - gm);
            sc_s[tid * 4 + 1] = scl * expf(pv.y - gm);
            sc_s[tid * 4 + 2] = scl * expf(pv.z - gm);
            sc_s[tid * 4 + 3] = scl * expf(pv.w - gm);
        }
    }
    // ---- convert + swizzled store: elem (c, v) at [c*128 + (v ^ 8*(c&7))] ----
    #pragma unroll
    for (int ph = 0; ph < 8; ph++) {
        const int c = cld + ph * 8;
        uint2 hp;
        hp.x = f16x2_pack(xv[ph].x, xv[ph].y);
        hp.y = f16x2_pack(xv[ph].z, xv[ph].w);
        const int off = c * 128 + (vld ^ (8 * (c & 7)));
        *(uint2*)&Xh[off] = hp;
    }
    __syncthreads();

    // ---- mma mainloop: warp = 16 vox rows x 64 co ----
    const int wrp  = tid >> 5;
    const int lane = tid & 31;
    const int v0   = wrp * 16;

    float acc[8][4];
    #pragma unroll
    for (int ni = 0; ni < 8; ni++)
        #pragma unroll
        for (int r = 0; r < 4; r++) acc[ni][r] = 0.f;

    const int jA   = lane & 7;
    const int sub  = lane >> 3;                // 0..3
    const int cOfA = (sub >> 1) * 8 + jA;
    const int vOfA = (sub & 1) * 8;
    const int niOfB = sub >> 1;
    const int kSelB = sub & 1;

    #pragma unroll
    for (int ki = 0; ki < 4; ki++) {
        const int k0 = ki * 16;
        uint32_t Ah[4];
        {
            const int c = k0 + cOfA;
            const int v = v0 + vOfA;
            const uint32_t off = (uint32_t)(c * 128 + (v ^ (8 * (c & 7)))) * 2u;
            ldmA(Ah, sbase + SM_XH + off);
        }
        #pragma unroll
        for (int np = 0; np < 4; np++) {       // ni pair {2np, 2np+1}
            const int n = (np * 2 + niOfB) * 8 + jA;
            const int k = k0 + 8 * kSelB;
            const uint32_t off = (uint32_t)(n * 64 + (k ^ (8 * (n & 7)))) * 2u;
            uint32_t Bh[4];
            ldmB4(Bh, sbase + SM_WH + off);
            mma_f16(acc[np * 2],     Ah, Bh);
            mma_f16(acc[np * 2 + 1], Ah, Bh + 2);
        }
    }
    __syncthreads();           // done with Xh/Wh smem; overlay Ds

    // ---- stage D to smem: Ds[co][vox], row stride 132 floats ----
    float* Ds = (float*)dsm;
    {
        const int g = lane >> 2, t4 = lane & 3;
        const int m = v0 + g;
        #pragma unroll
        for (int ni = 0; ni < 8; ni++) {
            const int n = ni * 8 + t4 * 2;
            Ds[n * 132 + m]           = acc[ni][0];
            Ds[(n + 1) * 132 + m]     = acc[ni][1];
            Ds[n * 132 + m + 8]       = acc[ni][2];
            Ds[(n + 1) * 132 + m + 8] = acc[ni][3];
        }
    }
    __syncthreads();

    // ---- epilogue: warp = 8 co rows, lane covers full 128-vox row (512B stores)
    {
        const int v = lane * 4;
        const float4 sv = *(const float4*)&sc_s[v];
        #pragma unroll
        for (int r = 0; r < 8; r++) {
            const int co = wrp * 8 + r;
            const float bvv = s_bv[co];
            float4 dv = *(const float4*)&Ds[co * 132 + v];
            dv.x = (dv.x + bvv) * sv.x;
            dv.y = (dv.y + bvv) * sv.y;
            dv.z = (dv.z + bvv) * sv.z;
            dv.w = (dv.w + bvv) * sv.w;
            *(float4*)&out[((size_t)(b * CC + co)) * NVOX + n0 + v] = dv;
        }
    }
}

// ---------------- host launcher ----------------
extern "C" void kernel_launch(void* const* d_in, const int* in_sizes, int n_in,
                              void* d_out, int out_size) {
    const float* x     = (const float*)d_in[0];
    const float* mask  = (const float*)d_in[1];
    const float* Wk    = (const float*)d_in[2];
    const float* bk    = (const float*)d_in[3];
    const float* Wv    = (const float*)d_in[4];
    const float* bv    = (const float*)d_in[5];
    const float* Wq    = (const float*)d_in[6];
    const float* bq    = (const float*)d_in[7];
    const float* h_tab = (const float*)d_in[8];
    const float* w_tab = (const float*)d_in[9];
    const float* d_tab = (const float*)d_in[10];
    float* out = (float*)d_out;

    cudaFuncSetAttribute(k_out_mma, cudaFuncAttributeMaxDynamicSharedMemorySize,
                         OUT_SMEM_DYN);

    k_wsplit <<<17, 256>>>(Wv);                     // includes scratch zeroing
    k_reduce <<<dim3(NVOX / 1024, BB), 256>>>(x, mask);   // 256 blocks, exact
    k_prep   <<<BB, 256>>>(Wk, bk, Wq, bq, h_tab, w_tab, d_tab);
    k_logits <<<dim3(NBLK_L, BB), 256>>>(x);
    k_finish <<<BB, NBLK_L>>>();
    k_out_mma<<<dim3(NVOX / TILE_V, BB), 256, OUT_SMEM_DYN>>>(x, bv, out);

    // output tuple tail: mask passthrough
    cudaMemcpyAsync(out + (size_t)BB * CC * NVOX, mask,
                    (size_t)BB * NVOX * sizeof(float),
                    cudaMemcpyDeviceToDevice, 0);
}

// round 16
// speedup vs baseline: 1.1576x; 1.0156x over previous
#include <cuda_runtime.h>
#include <cuda_fp16.h>
#include <cstdint>

#define BB 2
#define CC 64
#define HWD 64
#define NVOX (HWD*HWD*HWD)   /* 262144 */
#define TILE_V 128
#define NBLK_L 512           /* k_logits blocks per batch (512 vox each) */

// ---------------- device scratch (static, no allocation) ----------------
__device__ float    g_s[BB][CC];
__device__ float    g_mh[BB][HWD];
__device__ float    g_mw[BB][HWD];
__device__ float    g_md[BB][HWD];
__device__ float    g_M[BB];
__device__ float    g_u[BB][CC];
__device__ float    g_c0[BB];
__device__ float    g_qh[BB][HWD];
__device__ float    g_qw[BB][HWD];
__device__ float    g_qd[BB][HWD];
__device__ float    g_bmax[BB][NBLK_L];
__device__ float    g_bsum[BB][NBLK_L];
__device__ float    g_gmax[BB];
__device__ float    g_scale[BB];          // M / sumexp
__device__ float    g_logits[BB][NVOX];   // raw logits
__device__ unsigned short g_Wh[CC * CC];  // Wv fp16, swizzled [n][k^8(n&7)]

// ---------------- helpers ----------------
__device__ __forceinline__ uint32_t smem_u32(const void* p) {
    uint32_t a;
    asm("{ .reg .u64 t; cvta.to.shared.u64 t, %1; cvt.u32.u64 %0, t; }"
        : "=r"(a) : "l"(p));
    return a;
}
__device__ __forceinline__ uint32_t f16x2_pack(float v0, float v1) {
    uint32_t h;
    asm("cvt.rn.f16x2.f32 %0, %1, %2;" : "=r"(h) : "f"(v1), "f"(v0));
    return h;
}
__device__ __forceinline__ void ldmA(uint32_t* a, uint32_t addr) {
    asm volatile("ldmatrix.sync.aligned.m8n8.x4.trans.shared.b16 "
                 "{%0,%1,%2,%3}, [%4];"
                 : "=r"(a[0]), "=r"(a[1]), "=r"(a[2]), "=r"(a[3]) : "r"(addr));
}
__device__ __forceinline__ void ldmB4(uint32_t* b, uint32_t addr) {
    asm volatile("ldmatrix.sync.aligned.m8n8.x4.shared.b16 {%0,%1,%2,%3}, [%4];"
                 : "=r"(b[0]), "=r"(b[1]), "=r"(b[2]), "=r"(b[3]) : "r"(addr));
}
__device__ __forceinline__ void mma_f16(float* c, const uint32_t* a,
                                        const uint32_t* b) {
    asm volatile("mma.sync.aligned.m16n8k16.row.col.f32.f16.f16.f32 "
                 "{%0,%1,%2,%3}, {%4,%5,%6,%7}, {%8,%9}, {%0,%1,%2,%3};"
                 : "+f"(c[0]), "+f"(c[1]), "+f"(c[2]), "+f"(c[3])
                 : "r"(a[0]), "r"(a[1]), "r"(a[2]), "r"(a[3]),
                   "r"(b[0]), "r"(b[1]));
}

// ---------------- kernel W: zero scratch + convert Wv to fp16 (merged) ------
__global__ void k_wsplit(const float* __restrict__ Wv) {
    const int tid = threadIdx.x;
    if (blockIdx.x == 16) {       // zeroing block
        if (tid < CC)  { g_s[0][tid] = 0.f; g_s[1][tid] = 0.f; }
        if (tid < HWD) {
            g_mh[0][tid] = 0.f; g_mh[1][tid] = 0.f;
            g_mw[0][tid] = 0.f; g_mw[1][tid] = 0.f;
            g_md[0][tid] = 0.f; g_md[1][tid] = 0.f;
        }
        return;
    }
    int i = blockIdx.x * 256 + tid;
    int n = i >> 6, k = i & 63;
    const __half h = __float2half_rn(Wv[i]);
    int ks = k ^ (8 * (n & 7));
    g_Wh[n * 64 + ks] = __half_as_ushort(h);
}

// ---------------- kernel 1: masked reductions (float4) + mask passthrough ---
__global__ void __launch_bounds__(256) k_reduce(const float* __restrict__ x,
                                                const float* __restrict__ mask,
                                                float* __restrict__ out_tail) {
    const int b   = blockIdx.y;
    const float* xb = x    + (size_t)b * CC * NVOX;
    const float* mb = mask + (size_t)b * NVOX;
    __shared__ float ss[CC];
    __shared__ float sh[HWD], sw[HWD], sd[HWD];
    const int tid = threadIdx.x;
    if (tid < CC)  ss[tid] = 0.f;
    if (tid < HWD) { sh[tid] = 0.f; sw[tid] = 0.f; sd[tid] = 0.f; }
    __syncthreads();

    const int p = blockIdx.x * 256 + tid;      // quad index (exact cover)
    const int n = 4 * p;
    const float4 m = ((const float4*)mb)[p];
    // fused output-tuple tail: mask passthrough (saves the separate memcpy)
    ((float4*)(out_tail + (size_t)b * NVOX))[p] = m;

    const int d = n & 63, w = (n >> 6) & 63, h = n >> 12;
    const int lane = tid & 31;
    const float msum = m.x + m.y + m.z + m.w;

    // h marginal: warp-uniform
    {
        float s = msum;
        #pragma unroll
        for (int o = 16; o; o >>= 1) s += __shfl_xor_sync(0xffffffffu, s, o);
        if (lane == 0) atomicAdd(&sh[h], s);
    }
    // w marginal: uniform per 16-lane half
    {
        float s = msum;
        #pragma unroll
        for (int o = 8; o; o >>= 1) s += __shfl_xor_sync(0xffffffffu, s, o);
        if ((lane & 15) == 0) atomicAdd(&sw[w], s);
    }
    // d marginal: lanes L and L+16 share d values — fold, then 16 lanes atomic
    {
        float d0 = m.x + __shfl_xor_sync(0xffffffffu, m.x, 16);
        float d1 = m.y + __shfl_xor_sync(0xffffffffu, m.y, 16);
        float d2 = m.z + __shfl_xor_sync(0xffffffffu, m.z, 16);
        float d3 = m.w + __shfl_xor_sync(0xffffffffu, m.w, 16);
        if (lane < 16) {
            atomicAdd(&sd[d],     d0);
            atomicAdd(&sd[d + 1], d1);
            atomicAdd(&sd[d + 2], d2);
            atomicAdd(&sd[d + 3], d3);
        }
    }

    // channel-wise masked sums
    float acc[CC];
    #pragma unroll
    for (int c = 0; c < CC; c++) {
        const float4 v = ((const float4*)(xb + (size_t)c * NVOX))[p];
        acc[c] = m.x * v.x + m.y * v.y + m.z * v.z + m.w * v.w;
    }
    #pragma unroll
    for (int c = 0; c < CC; c++) {
        float v = acc[c];
        #pragma unroll
        for (int o = 16; o; o >>= 1) v += __shfl_xor_sync(0xffffffffu, v, o);
        if (lane == 0) atomicAdd(&ss[c], v);
    }
    __syncthreads();
    if (tid < CC)  atomicAdd(&g_s[b][tid],  ss[tid]);
    if (tid < HWD) {
        atomicAdd(&g_mh[b][tid], sh[tid]);
        atomicAdd(&g_mw[b][tid], sw[tid]);
        atomicAdd(&g_md[b][tid], sd[tid]);
    }
}

// ---------------- kernel 2: prep (256 thr = 64 outputs x 4 slices) ----------
__global__ void __launch_bounds__(256) k_prep(const float* __restrict__ Wk,
                                              const float* __restrict__ bk,
                                              const float* __restrict__ Wq,
                                              const float* __restrict__ bq,
                                              const float* __restrict__ h_tab,
                                              const float* __restrict__ w_tab,
                                              const float* __restrict__ d_tab) {
    const int b   = blockIdx.x;
    const int tid = threadIdx.x;
    const int t   = tid >> 2;
    const int sl  = tid & 3;
    __shared__ float qs[CC];
    __shared__ float red[CC];
    __shared__ float Msh;

    if (tid < HWD) red[tid] = g_mh[b][tid];
    __syncthreads();
    if (tid == 0) {
        float M = 0.f;
        #pragma unroll
        for (int i = 0; i < HWD; i++) M += red[i];
        Msh = M; g_M[b] = M;
    }
    __syncthreads();

    {
        float a = 0.f;
        #pragma unroll
        for (int i = 0; i < 16; i++) {
            const int c = sl * 16 + i;
            a += Wq[t * CC + c] * g_s[b][c];
            a += g_mh[b][c] * h_tab[c * CC + t];
            a += g_mw[b][c] * w_tab[c * CC + t];
            a += g_md[b][c] * d_tab[c * CC + t];
        }
        a += __shfl_xor_sync(0xffffffffu, a, 1);
        a += __shfl_xor_sync(0xffffffffu, a, 2);
        if (sl == 0) qs[t] = a / Msh + bq[t];
    }
    __syncthreads();

    {
        float u = 0.f, a1 = 0.f, a2 = 0.f, a3 = 0.f;
        #pragma unroll
        for (int i = 0; i < 16; i++) {
            const int ck = sl * 16 + i;
            const float q = qs[ck];
            u  += q * Wk[ck * CC + t];
            a1 += q * h_tab[t * CC + ck];
            a2 += q * w_tab[t * CC + ck];
            a3 += q * d_tab[t * CC + ck];
        }
        u  += __shfl_xor_sync(0xffffffffu, u, 1);
        u  += __shfl_xor_sync(0xffffffffu, u, 2);
        a1 += __shfl_xor_sync(0xffffffffu, a1, 1);
        a1 += __shfl_xor_sync(0xffffffffu, a1, 2);
        a2 += __shfl_xor_sync(0xffffffffu, a2, 1);
        a2 += __shfl_xor_sync(0xffffffffu, a2, 2);
        a3 += __shfl_xor_sync(0xffffffffu, a3, 1);
        a3 += __shfl_xor_sync(0xffffffffu, a3, 2);
        if (sl == 0) {
            g_u[b][t]  = u;
            g_qh[b][t] = a1; g_qw[b][t] = a2; g_qd[b][t] = a3;
        }
    }
    if (tid < CC) red[tid] = qs[tid] * bk[tid];
    __syncthreads();
    if (tid == 0) {
        float a = 0.f;
        #pragma unroll
        for (int i = 0; i < CC; i++) a += red[i];
        g_c0[b] = a;
    }
}

// ---------------- kernel 3: logits (float2) + block max + block expsum ------
__global__ void __launch_bounds__(256) k_logits(const float* __restrict__ x) {
    const int b = blockIdx.y;
    __shared__ float us[CC];
    __shared__ float wred[8];
    __shared__ float bmax_s;
    const int tid = threadIdx.x;
    if (tid < CC) us[tid] = g_u[b][tid];
    __syncthreads();
    const float* xb = x + (size_t)b * CC * NVOX;
    const float  c0 = g_c0[b];
    const int p = blockIdx.x * 256 + tid;
    const int n = 2 * p;
    float l0 = c0, l1 = c0;
    #pragma unroll
    for (int c = 0; c < CC; c++) {
        const float2 v = ((const float2*)(xb + (size_t)c * NVOX))[p];
        const float u = us[c];
        l0 += u * v.x;
        l1 += u * v.y;
    }
    const int d = n & 63, w = (n >> 6) & 63, h = n >> 12;
    const float pw = g_qh[b][h] + g_qw[b][w];
    l0 = (l0 + pw + g_qd[b][d])     * 0.125f;
    l1 = (l1 + pw + g_qd[b][d + 1]) * 0.125f;
    ((float2*)&g_logits[b][0])[p] = make_float2(l0, l1);

    // block max
    float mx = fmaxf(l0, l1);
    #pragma unroll
    for (int o = 16; o; o >>= 1) mx = fmaxf(mx, __shfl_xor_sync(0xffffffffu, mx, o));
    const int wid = tid >> 5;
    if ((tid & 31) == 0) wred[wid] = mx;
    __syncthreads();
    if (tid == 0) {
        float m = wred[0];
        #pragma unroll
        for (int j = 1; j < 8; j++) m = fmaxf(m, wred[j]);
        bmax_s = m;
    }
    __syncthreads();
    const float bm = bmax_s;

    // block sum of exp(l - bm)
    float s = expf(l0 - bm) + expf(l1 - bm);
    #pragma unroll
    for (int o = 16; o; o >>= 1) s += __shfl_xor_sync(0xffffffffu, s, o);
    if ((tid & 31) == 0) wred[wid] = s;
    __syncthreads();
    if (tid == 0) {
        float t = 0.f;
        #pragma unroll
        for (int j = 0; j < 8; j++) t += wred[j];
        g_bmax[b][blockIdx.x] = bm;
        g_bsum[b][blockIdx.x] = t;
    }
}

// ---------------- kernel 4: finish softmax stats (tiny) ----------------
__global__ void __launch_bounds__(NBLK_L) k_finish() {
    const int b = blockIdx.x;
    const int t = threadIdx.x;        // 512
    __shared__ float wred[16];
    __shared__ float gmax_s;
    const float bm = g_bmax[b][t];
    float m = bm;
    #pragma unroll
    for (int o = 16; o; o >>= 1) m = fmaxf(m, __shfl_xor_sync(0xffffffffu, m, o));
    if ((t & 31) == 0) wred[t >> 5] = m;
    __syncthreads();
    if (t == 0) {
        float g = wred[0];
        #pragma unroll
        for (int j = 1; j < 16; j++) g = fmaxf(g, wred[j]);
        gmax_s = g;
    }
    __syncthreads();
    const float gm = gmax_s;
    float s = g_bsum[b][t] * expf(bm - gm);
    #pragma unroll
    for (int o = 16; o; o >>= 1) s += __shfl_xor_sync(0xffffffffu, s, o);
    if ((t & 31) == 0) wred[t >> 5] = s;
    __syncthreads();
    if (t == 0) {
        float tot = 0.f;
        #pragma unroll
        for (int j = 0; j < 16; j++) tot += wred[j];
        g_gmax[b]  = gm;
        g_scale[b] = g_M[b] / tot;
    }
}

// ---------------- kernel 5: vals GEMM on mma.sync pure fp16 (R13 shape) -----
#define SM_XH 0
#define SM_WH 16384
#define OUT_SMEM_DYN 34048

__global__ void __launch_bounds__(256, 4) k_out_mma(const float* __restrict__ x,
                                                    const float* __restrict__ bv,
                                                    float* __restrict__ out) {
    extern __shared__ char dsm[];
    __shared__ float sc_s[TILE_V];
    __shared__ float s_bv[CC];

    const int tid = threadIdx.x;
    const int b   = blockIdx.y;
    const int n0  = blockIdx.x * TILE_V;
    const uint32_t sbase = smem_u32(dsm);

    unsigned short* Xh = (unsigned short*)(dsm + SM_XH);

    // ---- front-load x tile: 8 float4 per thread ----
    const float* xb = x + (size_t)b * CC * NVOX + n0;
    const int vld = (tid & 31) * 4;
    const int cld = tid >> 5;
    float4 xv[8];
    #pragma unroll
    for (int ph = 0; ph < 8; ph++)
        xv[ph] = *(const float4*)&xb[(size_t)(cld + ph * 8) * NVOX + vld];

    // ---- weights + bias + per-vox softmax scale (overlaps x-load latency) ----
    {
        const uint4* wh = (const uint4*)g_Wh;
        uint4* dh = (uint4*)(dsm + SM_WH);
        for (int i = tid; i < 512; i += 256) dh[i] = wh[i];
        if (tid < CC) s_bv[tid] = bv[tid];
        if (tid < 32) {
            const float scl = g_scale[b];
            const float gm  = g_gmax[b];
            float4 pv = *(const float4*)&g_logits[b][n0 + tid * 4];
            sc_s[tid * 4 + 0] = scl * expf(pv.x - gm);
            sc_s[tid * 4 + 1] = scl * expf(pv.y - gm);
            sc_s[tid * 4 + 2] = scl * expf(pv.z - gm);
            sc_s[tid * 4 + 3] = scl * expf(pv.w - gm);
        }
    }
    // ---- convert + swizzled store: elem (c, v) at [c*128 + (v ^ 8*(c&7))] ----
    #pragma unroll
    for (int ph = 0; ph < 8; ph++) {
        const int c = cld + ph * 8;
        uint2 hp;
        hp.x = f16x2_pack(xv[ph].x, xv[ph].y);
        hp.y = f16x2_pack(xv[ph].z, xv[ph].w);
        const int off = c * 128 + (vld ^ (8 * (c & 7)));
        *(uint2*)&Xh[off] = hp;
    }
    __syncthreads();

    // ---- mma mainloop: warp = 16 vox rows x 64 co ----
    const int wrp  = tid >> 5;
    const int lane = tid & 31;
    const int v0   = wrp * 16;

    float acc[8][4];
    #pragma unroll
    for (int ni = 0; ni < 8; ni++)
        #pragma unroll
        for (int r = 0; r < 4; r++) acc[ni][r] = 0.f;

    const int jA   = lane & 7;
    const int sub  = lane >> 3;                // 0..3
    const int cOfA = (sub >> 1) * 8 + jA;
    const int vOfA = (sub & 1) * 8;
    const int niOfB = sub >> 1;
    const int kSelB = sub & 1;

    #pragma unroll
    for (int ki = 0; ki < 4; ki++) {
        const int k0 = ki * 16;
        uint32_t Ah[4];
        {
            const int c = k0 + cOfA;
            const int v = v0 + vOfA;
            const uint32_t off = (uint32_t)(c * 128 + (v ^ (8 * (c & 7)))) * 2u;
            ldmA(Ah, sbase + SM_XH + off);
        }
        #pragma unroll
        for (int np = 0; np < 4; np++) {       // ni pair {2np, 2np+1}
            const int n = (np * 2 + niOfB) * 8 + jA;
            const int k = k0 + 8 * kSelB;
            const uint32_t off = (uint32_t)(n * 64 + (k ^ (8 * (n & 7)))) * 2u;
            uint32_t Bh[4];
            ldmB4(Bh, sbase + SM_WH + off);
            mma_f16(acc[np * 2],     Ah, Bh);
            mma_f16(acc[np * 2 + 1], Ah, Bh + 2);
        }
    }
    __syncthreads();           // done with Xh/Wh smem; overlay Ds

    // ---- stage D to smem: Ds[co][vox], row stride 132 floats ----
    float* Ds = (float*)dsm;
    {
        const int g = lane >> 2, t4 = lane & 3;
        const int m = v0 + g;
        #pragma unroll
        for (int ni = 0; ni < 8; ni++) {
            const int n = ni * 8 + t4 * 2;
            Ds[n * 132 + m]           = acc[ni][0];
            Ds[(n + 1) * 132 + m]     = acc[ni][1];
            Ds[n * 132 + m + 8]       = acc[ni][2];
            Ds[(n + 1) * 132 + m + 8] = acc[ni][3];
        }
    }
    __syncthreads();

    // ---- epilogue: warp = 8 co rows, lane covers full 128-vox row (512B stores)
    {
        const int v = lane * 4;
        const float4 sv = *(const float4*)&sc_s[v];
        #pragma unroll
        for (int r = 0; r < 8; r++) {
            const int co = wrp * 8 + r;
            const float bvv = s_bv[co];
            float4 dv = *(const float4*)&Ds[co * 132 + v];
            dv.x = (dv.x + bvv) * sv.x;
            dv.y = (dv.y + bvv) * sv.y;
            dv.z = (dv.z + bvv) * sv.z;
            dv.w = (dv.w + bvv) * sv.w;
            *(float4*)&out[((size_t)(b * CC + co)) * NVOX + n0 + v] = dv;
        }
    }
}

// ---------------- host launcher ----------------
extern "C" void kernel_launch(void* const* d_in, const int* in_sizes, int n_in,
                              void* d_out, int out_size) {
    const float* x     = (const float*)d_in[0];
    const float* mask  = (const float*)d_in[1];
    const float* Wk    = (const float*)d_in[2];
    const float* bk    = (const float*)d_in[3];
    const float* Wv    = (const float*)d_in[4];
    const float* bv    = (const float*)d_in[5];
    const float* Wq    = (const float*)d_in[6];
    const float* bq    = (const float*)d_in[7];
    const float* h_tab = (const float*)d_in[8];
    const float* w_tab = (const float*)d_in[9];
    const float* d_tab = (const float*)d_in[10];
    float* out = (float*)d_out;

    cudaFuncSetAttribute(k_out_mma, cudaFuncAttributeMaxDynamicSharedMemorySize,
                         OUT_SMEM_DYN);

    float* out_tail = out + (size_t)BB * CC * NVOX;

    k_wsplit <<<17, 256>>>(Wv);                               // + scratch zeroing
    k_reduce <<<dim3(NVOX / 1024, BB), 256>>>(x, mask, out_tail);  // + mask tail
    k_prep   <<<BB, 256>>>(Wk, bk, Wq, bq, h_tab, w_tab, d_tab);
    k_logits <<<dim3(NBLK_L, BB), 256>>>(x);
    k_finish <<<BB, NBLK_L>>>();
    k_out_mma<<<dim3(NVOX / TILE_V, BB), 256, OUT_SMEM_DYN>>>(x, bv, out);
}